// round 14
// baseline (speedup 1.0000x reference)
#include <cuda_runtime.h>
#include <math.h>
#include <stdint.h>

#define BATCH 4096
#define D     64
#define HDIM  256
#define G3    768
#define KC    208
#define KPAD  224
#define NK    20
#define WTS   258          // old-style Wt stride (gemm_cbm only)

#define ASTR  264          // A-tile row stride (floats): bank-conflict-free, 16B aligned
#define BSTR  36           // staged-B row stride (floats)
#define GISTR 776          // giS row stride
#define ZSTR  72           // zr row stride

typedef unsigned long long u64;

// ---------------- scratch (device globals: no allocation allowed) ----------------
__device__ float g_gi[(size_t)BATCH * G3];          // cbm @ W_ih[:,1:]^T + b_ih
__device__ float g_c1[(size_t)BATCH * HDIM];        // cbm @ W1[:,256:]^T + b1
__device__ float g_hs[(size_t)BATCH * D * HDIM];    // GRU hidden states
__device__ float g_ll[(size_t)BATCH * D];           // per-position log-likelihood

// ======================= packed f32x2 helpers =======================
__device__ __forceinline__ u64 pack2(float x, float y) {
    u64 r; asm("mov.b64 %0, {%1,%2};" : "=l"(r) : "f"(x), "f"(y)); return r;
}
__device__ __forceinline__ float2 unpack2(u64 v) {
    float2 f; asm("mov.b64 {%0,%1}, %2;" : "=f"(f.x), "=f"(f.y) : "l"(v)); return f;
}
__device__ __forceinline__ void ffma2(u64& d, u64 a, u64 b) {
    asm("fma.rn.f32x2 %0, %1, %2, %0;" : "+l"(d) : "l"(a), "l"(b));
}

// ---------------------------------------------------------------------------
// K-paired micro-kernel: acc2[8][4] += As[32 x 256] * B[256 x 256(k)]^T.
// f32x2 lanes hold even/odd-k partial sums (reduced to scalar in epilogue).
// A: smem [32][ASTR] K-major.  B: gmem K-major [g][ldb], staged per-kt into
// Bs[256][BSTR] as a pure copy (no transpose).  Thread (w,lane):
//   rows r = (lane>>3) + 4j  (j=0..7),  cols c = (lane&7) + 8w + 64i (i=0..3).
// All inner loads are LDS.128, conflict-free via the padded strides.
// ---------------------------------------------------------------------------
__device__ __forceinline__ void mmk256(
    u64 acc[8][4], const float* __restrict__ B, int ldb,
    const float* As, float* Bs, int tid)
{
    const int lane = tid & 31, w = tid >> 5;
    const int rg = lane >> 3;
    const int cg = (lane & 7) + 8 * w;
    const int u  = tid & 7, g0 = tid >> 3;
    const float* ar[8];
    const float* bg[4];
#pragma unroll
    for (int j = 0; j < 8; ++j) ar[j] = As + (rg + 4 * j) * ASTR;
#pragma unroll
    for (int i = 0; i < 4; ++i) bg[i] = Bs + (cg + 64 * i) * BSTR;
#pragma unroll 1
    for (int kt = 0; kt < 8; ++kt) {
        const int k0 = kt * 32;
#pragma unroll
        for (int j = 0; j < 8; ++j) {
            int g = g0 + 32 * j;
            float4 v = *(const float4*)(B + g * ldb + k0 + 4 * u);
            *(float4*)(Bs + g * BSTR + 4 * u) = v;
        }
        __syncthreads();
#pragma unroll
        for (int kq = 0; kq < 8; ++kq) {
            ulonglong2 av[8];
#pragma unroll
            for (int j = 0; j < 8; ++j)
                av[j] = *(const ulonglong2*)(ar[j] + k0 + 4 * kq);
#pragma unroll
            for (int i = 0; i < 4; ++i) {
                ulonglong2 bv = *(const ulonglong2*)(bg[i] + 4 * kq);
#pragma unroll
                for (int j = 0; j < 8; ++j) {
                    ffma2(acc[j][i], av[j].x, bv.x);
                    ffma2(acc[j][i], av[j].y, bv.y);
                }
            }
        }
        __syncthreads();
    }
}

// 64-output variant (layer 3; valid rows < 60 zero-padded). C = 1.
__device__ __forceinline__ void mmk64(
    u64 acc[8], const float* __restrict__ B, int ldb,
    const float* As, float* Bs, int tid)
{
    const int lane = tid & 31, w = tid >> 5;
    const int rg = lane >> 3;
    const int cg = (lane & 7) + 8 * w;      // 0..63
    const int u  = tid & 7, g0 = tid >> 3;  // g0 0..31
    const float* ar[8];
#pragma unroll
    for (int j = 0; j < 8; ++j) ar[j] = As + (rg + 4 * j) * ASTR;
    const float* bgp = Bs + cg * BSTR;
#pragma unroll 1
    for (int kt = 0; kt < 8; ++kt) {
        const int k0 = kt * 32;
#pragma unroll
        for (int j = 0; j < 2; ++j) {
            int g = g0 + 32 * j;
            float4 v = make_float4(0.f, 0.f, 0.f, 0.f);
            if (g < 60) v = *(const float4*)(B + g * ldb + k0 + 4 * u);
            *(float4*)(Bs + g * BSTR + 4 * u) = v;
        }
        __syncthreads();
#pragma unroll
        for (int kq = 0; kq < 8; ++kq) {
            ulonglong2 bv = *(const ulonglong2*)(bgp + 4 * kq);
#pragma unroll
            for (int j = 0; j < 8; ++j) {
                ulonglong2 av = *(const ulonglong2*)(ar[j] + k0 + 4 * kq);
                ffma2(acc[j], av.x, bv.x);
                ffma2(acc[j], av.y, bv.y);
            }
        }
        __syncthreads();
    }
}

// ---------------------------------------------------------------------------
// Kernel 1: out = cbm @ Bmat[:, colOff:colOff+208]^T + bias  (unchanged R12)
// ---------------------------------------------------------------------------
__global__ void __launch_bounds__(256) gemm_cbm_kernel(
    const float* __restrict__ c, const float* __restrict__ bb, const float* __restrict__ mmat,
    const float* __restrict__ Bmat, int ldb, int colOff,
    const float* __restrict__ bias, int which, int ldout)
{
    extern __shared__ float sm[];
    float* As = sm;                 // 32*224
    float* Wt = As + 32 * KPAD;     // 32*258
    float* outp = which ? g_c1 : g_gi;

    const int tid  = threadIdx.x;
    const int lane = tid & 31, w = tid >> 5;
    const int row0 = blockIdx.x * 32;
    const int gb   = blockIdx.y * 256;

    for (int idx = tid; idx < 32 * KPAD; idx += 256) {
        int r = idx / KPAD, j = idx - r * KPAD;
        int br = row0 + r;
        float v = 0.f;
        if (j < 80)        v = c[br * 80 + j];
        else if (j < 144)  v = bb[br * 64 + (j - 80)];
        else if (j < KC)   v = mmat[br * 64 + (j - 144)];
        As[idx] = v;
    }
    __syncthreads();

    u64 acc[4][4];
#pragma unroll
    for (int j = 0; j < 4; ++j)
#pragma unroll
        for (int i = 0; i < 4; ++i) acc[j][i] = 0ull;

#pragma unroll 1
    for (int kt = 0; kt < 7; ++kt) {
        const int k0 = kt * 32;
        const int kcol = k0 + lane;
#pragma unroll
        for (int it = 0; it < 32; ++it) {
            int g = it * 8 + w;
            float v = 0.f;
            if (kcol < KC) v = Bmat[(gb + g) * ldb + colOff + kcol];
            Wt[lane * WTS + g] = v;
        }
        __syncthreads();
#pragma unroll
        for (int kk = 0; kk < 32; ++kk) {
            float s0 = As[(w +  0) * KPAD + k0 + kk];
            float s1 = As[(w +  8) * KPAD + k0 + kk];
            float s2 = As[(w + 16) * KPAD + k0 + kk];
            float s3 = As[(w + 24) * KPAD + k0 + kk];
            u64 a0 = pack2(s0, s0), a1 = pack2(s1, s1);
            u64 a2 = pack2(s2, s2), a3 = pack2(s3, s3);
            const float* wbase = Wt + kk * WTS + 2 * lane;
#pragma unroll
            for (int i = 0; i < 4; ++i) {
                u64 wp = *(const u64*)(wbase + 64 * i);
                ffma2(acc[0][i], a0, wp);
                ffma2(acc[1][i], a1, wp);
                ffma2(acc[2][i], a2, wp);
                ffma2(acc[3][i], a3, wp);
            }
        }
        __syncthreads();
    }
#pragma unroll
    for (int j = 0; j < 4; ++j) {
        int r = row0 + w + 8 * j;
#pragma unroll
        for (int i = 0; i < 4; ++i) {
            int cc = gb + 2 * lane + 64 * i;
            float2 av = unpack2(acc[j][i]);
            float2 bi = *(const float2*)(bias + cc);
            float2 ov; ov.x = av.x + bi.x; ov.y = av.y + bi.y;
            *(float2*)(outp + (size_t)r * ldout + cc) = ov;
        }
    }
}

// ---------------------------------------------------------------------------
// Kernel 2: persistent batch-split GRU. 128 CTAs x 32 rows, 64 steps.
// ---------------------------------------------------------------------------
__global__ void __launch_bounds__(256) gru_kernel(
    const float* __restrict__ z, const float* __restrict__ Wih,
    const float* __restrict__ Whh, const float* __restrict__ bhh_g)
{
    extern __shared__ float sm[];
    float* hS   = sm;                        // 32*ASTR  = 8448
    float* giS  = hS   + 32 * ASTR;          // 32*GISTR = 24832
    float* Bs   = giS  + 32 * GISTR;         // 256*BSTR = 9216
    float* zr   = Bs   + 256 * BSTR;         // 32*ZSTR  = 2304
    float* wzS  = zr   + 32 * ZSTR;          // 768
    float* bhhS = wzS  + 768;                // 768

    const int tid  = threadIdx.x;
    const int lane = tid & 31, w = tid >> 5;
    const int rg   = lane >> 3;
    const int cgb  = (lane & 7) + 8 * w;
    const int row0 = blockIdx.x * 32;

    for (int i = tid; i < 32 * ASTR; i += 256) hS[i] = 0.f;
    for (int idx = tid; idx < 32 * 768; idx += 256) {
        int r = idx / 768, gg = idx - r * 768;
        giS[r * GISTR + gg] = g_gi[(size_t)row0 * G3 + idx];
    }
    for (int idx = tid; idx < 32 * 64; idx += 256) {
        int r = idx >> 6, tt = idx & 63;
        zr[r * ZSTR + tt] = z[(size_t)(row0 + r) * D + tt];
    }
    for (int i = tid; i < 768; i += 256) { wzS[i] = Wih[i * 209]; bhhS[i] = bhh_g[i]; }
    __syncthreads();

    float Rn[8][4];

    for (int t = 0; t < D; ++t) {
        float zp[8];
#pragma unroll
        for (int j = 0; j < 8; ++j)
            zp[j] = (t == 0) ? -1.f : zr[(rg + 4 * j) * ZSTR + (t - 1)];

        u64 acc[8][4];
        // ---- chunk r (gate rows 0..255) ----
#pragma unroll
        for (int j = 0; j < 8; ++j)
#pragma unroll
            for (int i = 0; i < 4; ++i) acc[j][i] = 0ull;
        mmk256(acc, Whh, 256, hS, Bs, tid);
#pragma unroll
        for (int j = 0; j < 8; ++j) {
            int r = rg + 4 * j;
            const float* gir = giS + r * GISTR;
#pragma unroll
            for (int i = 0; i < 4; ++i) {
                int g = cgb + 64 * i;
                float2 p = unpack2(acc[j][i]);
                float gate = p.x + p.y + gir[g] + zp[j] * wzS[g] + bhhS[g];
                Rn[j][i] = 1.f / (1.f + expf(-gate));
            }
        }
        // ---- chunk n (gate rows 512..767), r-gate in registers ----
#pragma unroll
        for (int j = 0; j < 8; ++j)
#pragma unroll
            for (int i = 0; i < 4; ++i) acc[j][i] = 0ull;
        mmk256(acc, Whh + 512 * 256, 256, hS, Bs, tid);
#pragma unroll
        for (int j = 0; j < 8; ++j) {
            int r = rg + 4 * j;
            const float* gir = giS + r * GISTR;
#pragma unroll
            for (int i = 0; i < 4; ++i) {
                int g = 512 + cgb + 64 * i;
                float2 p = unpack2(acc[j][i]);
                float nin = gir[g] + zp[j] * wzS[g] + Rn[j][i] * (p.x + p.y + bhhS[g]);
                Rn[j][i] = tanhf(nin);
            }
        }
        // ---- chunk u (gate rows 256..511), then h update ----
#pragma unroll
        for (int j = 0; j < 8; ++j)
#pragma unroll
            for (int i = 0; i < 4; ++i) acc[j][i] = 0ull;
        mmk256(acc, Whh + 256 * 256, 256, hS, Bs, tid);
#pragma unroll
        for (int j = 0; j < 8; ++j) {
            int r = rg + 4 * j;
            const float* gir = giS + r * GISTR;
#pragma unroll
            for (int i = 0; i < 4; ++i) {
                int cth = cgb + 64 * i;
                int g = 256 + cth;
                float2 p = unpack2(acc[j][i]);
                float uu = 1.f / (1.f + expf(-(gir[g] + zp[j] * wzS[g] + p.x + p.y + bhhS[g])));
                float hold = hS[r * ASTR + cth];
                float hn = (1.f - uu) * Rn[j][i] + uu * hold;
                hS[r * ASTR + cth] = hn;
                g_hs[((size_t)(row0 + r) * D + t) * HDIM + cth] = hn;
            }
        }
        __syncthreads();   // h writes visible before next step's A reads
    }
}

// ---------------------------------------------------------------------------
// Kernel 3: fused MLP + mixture log-likelihood. 8192 CTAs, 32 positions each.
// ---------------------------------------------------------------------------
__global__ void __launch_bounds__(256) mlp_kernel(
    const float* __restrict__ z,
    const float* __restrict__ W1, const float* __restrict__ W2, const float* __restrict__ W3,
    const float* __restrict__ b2, const float* __restrict__ b3)
{
    extern __shared__ float sm[];
    float* A   = sm;                  // 32*ASTR
    float* O   = A   + 32 * ASTR;     // 32*ASTR
    float* Bs  = O   + 32 * ASTR;     // 256*BSTR
    float* prm = Bs  + 256 * BSTR;    // 32*66
    float* c1s = prm + 32 * 66;       // 256
    float* b2s = c1s + 256;           // 256
    float* b3s = b2s + 256;           // 64
    float* zs  = b3s + 64;            // 32

    const int tid  = threadIdx.x;
    const int lane = tid & 31, w = tid >> 5;
    const int rg   = lane >> 3;
    const int cgb  = (lane & 7) + 8 * w;
    const int bId  = blockIdx.x >> 1;
    const int t0   = (blockIdx.x & 1) * 32;
    const size_t hbase = ((size_t)bId * D + t0) * HDIM;

    {
        const float* src = g_hs + hbase;
        for (int idx = tid; idx < 2048; idx += 256) {
            int r = idx >> 6, q = idx & 63;
            *(float4*)(A + r * ASTR + 4 * q) = *(const float4*)(src + r * 256 + 4 * q);
        }
    }
    if (tid < 256) { c1s[tid] = g_c1[(size_t)bId * HDIM + tid]; b2s[tid] = b2[tid]; }
    if (tid < 64)  b3s[tid] = (tid < 60) ? b3[tid] : 0.f;
    if (tid < 32)  zs[tid] = z[(size_t)bId * D + t0 + tid];
    // first stage-sync inside mmk256 covers these writes

    u64 acc[8][4];
    // ---- layer 1: A @ W1[:, :256]^T, +c1 (has b1 + cbm part), tanh -> O ----
#pragma unroll
    for (int j = 0; j < 8; ++j)
#pragma unroll
        for (int i = 0; i < 4; ++i) acc[j][i] = 0ull;
    mmk256(acc, W1, 464, A, Bs, tid);
#pragma unroll
    for (int j = 0; j < 8; ++j) {
        int r = rg + 4 * j;
#pragma unroll
        for (int i = 0; i < 4; ++i) {
            int cc = cgb + 64 * i;
            float2 p = unpack2(acc[j][i]);
            O[r * ASTR + cc] = tanhf(p.x + p.y + c1s[cc]);
        }
    }
    // ---- layer 2: O @ W2^T + b2, tanh -> A ----
#pragma unroll
    for (int j = 0; j < 8; ++j)
#pragma unroll
        for (int i = 0; i < 4; ++i) acc[j][i] = 0ull;
    mmk256(acc, W2, 256, O, Bs, tid);
#pragma unroll
    for (int j = 0; j < 8; ++j) {
        int r = rg + 4 * j;
#pragma unroll
        for (int i = 0; i < 4; ++i) {
            int cc = cgb + 64 * i;
            float2 p = unpack2(acc[j][i]);
            A[r * ASTR + cc] = tanhf(p.x + p.y + b2s[cc]);
        }
    }
    // ---- layer 3: A @ W3^T + b3 (N=60 padded 64) -> prm ----
    u64 acc3[8];
#pragma unroll
    for (int j = 0; j < 8; ++j) acc3[j] = 0ull;
    mmk64(acc3, W3, 256, A, Bs, tid);
#pragma unroll
    for (int j = 0; j < 8; ++j) {
        int r = rg + 4 * j;
        float2 p = unpack2(acc3[j]);
        prm[r * 66 + cgb] = p.x + p.y + b3s[cgb];
    }
    __syncthreads();

    // ---- mixture log-likelihood epilogue (1 thread per row) ----
    if (tid < 32) {
        const int row = tid;
        const float zt = zs[row];
        const float HALF_L2PI = 0.91893853320467274178f;   // 0.5*log(2*pi)
        float av[NK];
        float m1 = -1e30f, m2 = -1e30f;
#pragma unroll
        for (int k = 0; k < NK; ++k) {
            float lg = prm[row * 66 + k];
            float mu = prm[row * 66 + 20 + k];
            float ls = prm[row * 66 + 40 + k];
            float dd = (zt - mu) * expf(-ls);
            float a  = lg - ls - HALF_L2PI - 0.5f * dd * dd;
            av[k] = a;
            m1 = fmaxf(m1, a);
            m2 = fmaxf(m2, lg);
        }
        float s1 = 0.f, s2 = 0.f;
#pragma unroll
        for (int k = 0; k < NK; ++k) {
            s1 += expf(av[k] - m1);
            s2 += expf(prm[row * 66 + k] - m2);
        }
        g_ll[(size_t)bId * D + t0 + row] = (m1 + logf(s1)) - (m2 + logf(s2));
    }
}

// ---------------------------------------------------------------------------
// Kernel 4: masked sum (sort of 0/1 mask == prefix count). One warp per row.
// ---------------------------------------------------------------------------
__global__ void reduce_kernel(const float* __restrict__ bmat,
                              const float* __restrict__ mmat,
                              float* __restrict__ out)
{
    int gwarp = (blockIdx.x * blockDim.x + threadIdx.x) >> 5;
    int lane  = threadIdx.x & 31;
    if (gwarp >= BATCH) return;
    const float* br = bmat + (size_t)gwarp * D;
    const float* mr = mmat + (size_t)gwarp * D;
    bool q0 = (mr[lane]      > 0.5f) && (br[lane]      < 0.5f);
    bool q1 = (mr[lane + 32] > 0.5f) && (br[lane + 32] < 0.5f);
    int count = __popc(__ballot_sync(0xffffffffu, q0))
              + __popc(__ballot_sync(0xffffffffu, q1));
    float s = 0.f;
    const float* ll = g_ll + (size_t)gwarp * D;
    if (lane      < count) s += ll[lane];
    if (lane + 32 < count) s += ll[lane + 32];
#pragma unroll
    for (int off = 16; off > 0; off >>= 1)
        s += __shfl_xor_sync(0xffffffffu, s, off);
    if (lane == 0) out[gwarp] = s;
}

// ---------------------------------------------------------------------------
extern "C" void kernel_launch(void* const* d_in, const int* in_sizes, int n_in,
                              void* d_out, int out_size)
{
    (void)in_sizes; (void)n_in; (void)out_size;
    const float* z    = (const float*)d_in[0];
    const float* c    = (const float*)d_in[1];
    const float* b_   = (const float*)d_in[2];
    const float* m_   = (const float*)d_in[3];
    const float* W_ih = (const float*)d_in[4];
    const float* W_hh = (const float*)d_in[5];
    const float* b_ih = (const float*)d_in[6];
    const float* b_hh = (const float*)d_in[7];
    const float* W1   = (const float*)d_in[8];
    const float* b1   = (const float*)d_in[9];
    const float* W2   = (const float*)d_in[10];
    const float* b2   = (const float*)d_in[11];
    const float* W3   = (const float*)d_in[12];
    const float* b3   = (const float*)d_in[13];
    float* out = (float*)d_out;

    const size_t smem_cbm = (32 * KPAD + 32 * WTS) * sizeof(float);
    const size_t smem_gru = (32 * ASTR + 32 * GISTR + 256 * BSTR + 32 * ZSTR + 768 + 768)
                            * sizeof(float);
    const size_t smem_mlp = (32 * ASTR * 2 + 256 * BSTR + 32 * 66 + 256 + 256 + 64 + 32)
                            * sizeof(float);

    cudaFuncSetAttribute((const void*)gemm_cbm_kernel,
                         cudaFuncAttributeMaxDynamicSharedMemorySize, (int)smem_cbm);
    cudaFuncSetAttribute((const void*)gru_kernel,
                         cudaFuncAttributeMaxDynamicSharedMemorySize, (int)smem_gru);
    cudaFuncSetAttribute((const void*)mlp_kernel,
                         cudaFuncAttributeMaxDynamicSharedMemorySize, (int)smem_mlp);

    gemm_cbm_kernel<<<dim3(128, 3), 256, smem_cbm>>>(c, b_, m_, W_ih, 209, 1, b_ih, 0, G3);
    gemm_cbm_kernel<<<dim3(128, 1), 256, smem_cbm>>>(c, b_, m_, W1, 464, 256, b1, 1, HDIM);
    gru_kernel<<<128, 256, smem_gru>>>(z, W_ih, W_hh, b_hh);
    mlp_kernel<<<BATCH * 2, 256, smem_mlp>>>(z, W1, W2, W3, b2, b3);
    reduce_kernel<<<(BATCH * 32) / 256, 256>>>(b_, m_, out);
}

// round 15
// speedup vs baseline: 1.1761x; 1.1761x over previous
#include <cuda_runtime.h>
#include <math.h>
#include <stdint.h>

#define BATCH 4096
#define D     64
#define HDIM  256
#define G3    768
#define KC    208
#define KPAD  224
#define NK    20
#define WTS   258          // Wt stride (even -> 8B-aligned pairs, 2-way STS conflict only)

typedef unsigned long long u64;

// ---------------- scratch (device globals: no allocation allowed) ----------------
__device__ float g_gi[(size_t)BATCH * G3];          // cbm @ W_ih[:,1:]^T + b_ih
__device__ float g_c1[(size_t)BATCH * HDIM];        // cbm @ W1[:,256:]^T + b1
__device__ float g_hs[(size_t)BATCH * D * HDIM];    // GRU hidden states
__device__ float g_ll[(size_t)BATCH * D];           // per-position log-likelihood

// ======================= packed f32x2 helpers =======================
__device__ __forceinline__ u64 pack2(float x, float y) {
    u64 r; asm("mov.b64 %0, {%1,%2};" : "=l"(r) : "f"(x), "f"(y)); return r;
}
__device__ __forceinline__ float2 unpack2(u64 v) {
    float2 f; asm("mov.b64 {%0,%1}, %2;" : "=f"(f.x), "=f"(f.y) : "l"(v)); return f;
}
__device__ __forceinline__ void ffma2(u64& d, u64 a, u64 b) {
    asm("fma.rn.f32x2 %0, %1, %2, %0;" : "+l"(d) : "l"(a), "l"(b));
}

// ======================= fast transcendentals =======================
// sigmoid: no cancellation; abs err ~1e-7.
__device__ __forceinline__ float fsig(float x) {
    return __fdividef(1.f, 1.f + __expf(-x));
}
// tanh: 1 - 2/(e^{2x}+1); saturates correctly at +/-inf; abs err ~1e-7.
__device__ __forceinline__ float ftanh(float x) {
    return 1.f - __fdividef(2.f, __expf(2.f * x) + 1.f);
}

// ---------------------------------------------------------------------------
// Packed micro-kernel (R12): acc[4][4] f32x2 pairs += As[32x256] * B^T.
// Thread owns rows w+8j, column pairs 2*lane+64*i. Used by MLP (2 CTAs/SM).
// ---------------------------------------------------------------------------
__device__ __forceinline__ void mm2_chunk256(
    u64 acc[4][4], const float* __restrict__ Bmat, int ldb,
    const float* As, float* Wt, int tid)
{
    const int lane = tid & 31;
    const int w    = tid >> 5;
#pragma unroll 1
    for (int kt = 0; kt < 8; ++kt) {
        const int k0 = kt * 32;
#pragma unroll
        for (int it = 0; it < 32; ++it) {
            int g = it * 8 + w;
            Wt[lane * WTS + g] = Bmat[g * ldb + k0 + lane];
        }
        __syncthreads();
#pragma unroll
        for (int kk = 0; kk < 32; ++kk) {
            float s0 = As[(w +  0) * 256 + k0 + kk];
            float s1 = As[(w +  8) * 256 + k0 + kk];
            float s2 = As[(w + 16) * 256 + k0 + kk];
            float s3 = As[(w + 24) * 256 + k0 + kk];
            u64 a0 = pack2(s0, s0), a1 = pack2(s1, s1);
            u64 a2 = pack2(s2, s2), a3 = pack2(s3, s3);
            const float* wbase = Wt + kk * WTS + 2 * lane;
#pragma unroll
            for (int i = 0; i < 4; ++i) {
                u64 wp = *(const u64*)(wbase + 64 * i);
                ffma2(acc[0][i], a0, wp);
                ffma2(acc[1][i], a1, wp);
                ffma2(acc[2][i], a2, wp);
                ffma2(acc[3][i], a3, wp);
            }
        }
        __syncthreads();
    }
}

// ---------------------------------------------------------------------------
// Prefetch variant (GRU only; 1 CTA/SM -> registers free): kt+1's W values
// are LDG'd into registers during kt's compute, hiding L2 latency.
// ---------------------------------------------------------------------------
__device__ __forceinline__ void mm2_chunk256_pf(
    u64 acc[4][4], const float* __restrict__ Bmat, int ldb,
    const float* As, float* Wt, int tid)
{
    const int lane = tid & 31;
    const int w    = tid >> 5;
    const float* bp = Bmat + lane;
    float pre[32];
#pragma unroll
    for (int it = 0; it < 32; ++it)
        pre[it] = bp[(it * 8 + w) * ldb];            // kt = 0
#pragma unroll 1
    for (int kt = 0; kt < 8; ++kt) {
        __syncthreads();                             // prev-kt consumers done
#pragma unroll
        for (int it = 0; it < 32; ++it)
            Wt[lane * WTS + it * 8 + w] = pre[it];
        if (kt < 7) {
            const float* bn = bp + (kt + 1) * 32;
#pragma unroll
            for (int it = 0; it < 32; ++it)          // prefetch kt+1 (latency
                pre[it] = bn[(it * 8 + w) * ldb];    // hidden behind compute)
        }
        __syncthreads();                             // Wt ready
        const int k0 = kt * 32;
#pragma unroll
        for (int kk = 0; kk < 32; ++kk) {
            float s0 = As[(w +  0) * 256 + k0 + kk];
            float s1 = As[(w +  8) * 256 + k0 + kk];
            float s2 = As[(w + 16) * 256 + k0 + kk];
            float s3 = As[(w + 24) * 256 + k0 + kk];
            u64 a0 = pack2(s0, s0), a1 = pack2(s1, s1);
            u64 a2 = pack2(s2, s2), a3 = pack2(s3, s3);
            const float* wbase = Wt + kk * WTS + 2 * lane;
#pragma unroll
            for (int i = 0; i < 4; ++i) {
                u64 wp = *(const u64*)(wbase + 64 * i);
                ffma2(acc[0][i], a0, wp);
                ffma2(acc[1][i], a1, wp);
                ffma2(acc[2][i], a2, wp);
                ffma2(acc[3][i], a3, wp);
            }
        }
    }
    __syncthreads();
}

// ---------------------------------------------------------------------------
// Kernel 1: out = cbm @ Bmat[:, colOff:colOff+208]^T + bias   (K=208 pad 224)
// ---------------------------------------------------------------------------
__global__ void __launch_bounds__(256) gemm_cbm_kernel(
    const float* __restrict__ c, const float* __restrict__ bb, const float* __restrict__ mmat,
    const float* __restrict__ Bmat, int ldb, int colOff,
    const float* __restrict__ bias, int which, int ldout)
{
    extern __shared__ float sm[];
    float* As = sm;                 // 32*224
    float* Wt = As + 32 * KPAD;     // 32*258
    float* outp = which ? g_c1 : g_gi;

    const int tid  = threadIdx.x;
    const int lane = tid & 31, w = tid >> 5;
    const int row0 = blockIdx.x * 32;
    const int gb   = blockIdx.y * 256;

    for (int idx = tid; idx < 32 * KPAD; idx += 256) {
        int r = idx / KPAD, j = idx - r * KPAD;
        int br = row0 + r;
        float v = 0.f;
        if (j < 80)        v = c[br * 80 + j];
        else if (j < 144)  v = bb[br * 64 + (j - 80)];
        else if (j < KC)   v = mmat[br * 64 + (j - 144)];
        As[idx] = v;
    }
    __syncthreads();

    u64 acc[4][4];
#pragma unroll
    for (int j = 0; j < 4; ++j)
#pragma unroll
        for (int i = 0; i < 4; ++i) acc[j][i] = 0ull;

#pragma unroll 1
    for (int kt = 0; kt < 7; ++kt) {
        const int k0 = kt * 32;
        const int kcol = k0 + lane;
#pragma unroll
        for (int it = 0; it < 32; ++it) {
            int g = it * 8 + w;
            float v = 0.f;
            if (kcol < KC) v = Bmat[(gb + g) * ldb + colOff + kcol];
            Wt[lane * WTS + g] = v;
        }
        __syncthreads();
#pragma unroll
        for (int kk = 0; kk < 32; ++kk) {
            float s0 = As[(w +  0) * KPAD + k0 + kk];
            float s1 = As[(w +  8) * KPAD + k0 + kk];
            float s2 = As[(w + 16) * KPAD + k0 + kk];
            float s3 = As[(w + 24) * KPAD + k0 + kk];
            u64 a0 = pack2(s0, s0), a1 = pack2(s1, s1);
            u64 a2 = pack2(s2, s2), a3 = pack2(s3, s3);
            const float* wbase = Wt + kk * WTS + 2 * lane;
#pragma unroll
            for (int i = 0; i < 4; ++i) {
                u64 wp = *(const u64*)(wbase + 64 * i);
                ffma2(acc[0][i], a0, wp);
                ffma2(acc[1][i], a1, wp);
                ffma2(acc[2][i], a2, wp);
                ffma2(acc[3][i], a3, wp);
            }
        }
        __syncthreads();
    }
#pragma unroll
    for (int j = 0; j < 4; ++j) {
        int r = row0 + w + 8 * j;
#pragma unroll
        for (int i = 0; i < 4; ++i) {
            int cc = gb + 2 * lane + 64 * i;
            float2 av = unpack2(acc[j][i]);
            float2 bi = *(const float2*)(bias + cc);
            float2 ov; ov.x = av.x + bi.x; ov.y = av.y + bi.y;
            *(float2*)(outp + (size_t)r * ldout + cc) = ov;
        }
    }
}

// ---------------------------------------------------------------------------
// Kernel 2: persistent batch-split GRU. 128 CTAs x 32 rows, 64 steps.
// ---------------------------------------------------------------------------
__global__ void __launch_bounds__(256) gru_kernel(
    const float* __restrict__ z, const float* __restrict__ Wih,
    const float* __restrict__ Whh, const float* __restrict__ bhh_g)
{
    extern __shared__ float sm[];
    float* hS   = sm;                   // 32*256
    float* giS  = hS  + 32 * 256;       // 32*768
    float* Wt   = giS + 32 * 768;       // 32*258
    float* zr   = Wt  + 32 * WTS;       // 32*64
    float* wzS  = zr  + 32 * 64;        // 768
    float* bhhS = wzS + 768;            // 768

    const int tid  = threadIdx.x;
    const int lane = tid & 31, w = tid >> 5;
    const int row0 = blockIdx.x * 32;

    for (int i = tid; i < 32 * 256; i += 256) hS[i] = 0.f;
    for (int i = tid; i < 32 * 768; i += 256) giS[i] = g_gi[(size_t)row0 * G3 + i];
    for (int i = tid; i < 32 * 64;  i += 256) zr[i]  = z[(size_t)row0 * D + i];
    for (int i = tid; i < 768; i += 256) { wzS[i] = Wih[i * 209]; bhhS[i] = bhh_g[i]; }
    __syncthreads();

    float Rn[4][8];   // r-gate then n-gate, mapping (j, 2i / 2i+1)

    for (int t = 0; t < D; ++t) {
        float zp[4];
#pragma unroll
        for (int j = 0; j < 4; ++j)
            zp[j] = (t == 0) ? -1.f : zr[(w + 8 * j) * 64 + (t - 1)];

        u64 acc[4][4];
        // ---- chunk r (gate rows 0..255) ----
#pragma unroll
        for (int j = 0; j < 4; ++j)
#pragma unroll
            for (int i = 0; i < 4; ++i) acc[j][i] = 0ull;
        mm2_chunk256_pf(acc, Whh, 256, hS, Wt, tid);
#pragma unroll
        for (int j = 0; j < 4; ++j) {
            int r = w + 8 * j;
#pragma unroll
            for (int i = 0; i < 4; ++i) {
                int g = 2 * lane + 64 * i;
                float2 av = unpack2(acc[j][i]);
                float2 gi2 = *(const float2*)(giS + r * 768 + g);
                float2 wz2 = *(const float2*)(wzS + g);
                float2 bh2 = *(const float2*)(bhhS + g);
                Rn[j][2 * i]     = fsig(gi2.x + zp[j] * wz2.x + av.x + bh2.x);
                Rn[j][2 * i + 1] = fsig(gi2.y + zp[j] * wz2.y + av.y + bh2.y);
            }
        }
        // ---- chunk n (gate rows 512..767), r in registers ----
#pragma unroll
        for (int j = 0; j < 4; ++j)
#pragma unroll
            for (int i = 0; i < 4; ++i) acc[j][i] = 0ull;
        mm2_chunk256_pf(acc, Whh + 512 * 256, 256, hS, Wt, tid);
#pragma unroll
        for (int j = 0; j < 4; ++j) {
            int r = w + 8 * j;
#pragma unroll
            for (int i = 0; i < 4; ++i) {
                int g = 512 + 2 * lane + 64 * i;
                float2 av = unpack2(acc[j][i]);
                float2 gi2 = *(const float2*)(giS + r * 768 + g);
                float2 wz2 = *(const float2*)(wzS + g);
                float2 bh2 = *(const float2*)(bhhS + g);
                float nx = gi2.x + zp[j] * wz2.x + Rn[j][2 * i]     * (av.x + bh2.x);
                float ny = gi2.y + zp[j] * wz2.y + Rn[j][2 * i + 1] * (av.y + bh2.y);
                Rn[j][2 * i]     = ftanh(nx);
                Rn[j][2 * i + 1] = ftanh(ny);
            }
        }
        // ---- chunk u (gate rows 256..511), then h update ----
#pragma unroll
        for (int j = 0; j < 4; ++j)
#pragma unroll
            for (int i = 0; i < 4; ++i) acc[j][i] = 0ull;
        mm2_chunk256_pf(acc, Whh + 256 * 256, 256, hS, Wt, tid);
#pragma unroll
        for (int j = 0; j < 4; ++j) {
            int r = w + 8 * j;
#pragma unroll
            for (int i = 0; i < 4; ++i) {
                int cidx = 2 * lane + 64 * i;
                int g = 256 + cidx;
                float2 av = unpack2(acc[j][i]);
                float2 gi2 = *(const float2*)(giS + r * 768 + g);
                float2 wz2 = *(const float2*)(wzS + g);
                float2 bh2 = *(const float2*)(bhhS + g);
                float ux = fsig(gi2.x + zp[j] * wz2.x + av.x + bh2.x);
                float uy = fsig(gi2.y + zp[j] * wz2.y + av.y + bh2.y);
                float2 hold = *(const float2*)(hS + r * 256 + cidx);
                float2 hn;
                hn.x = Rn[j][2 * i]     + ux * (hold.x - Rn[j][2 * i]);
                hn.y = Rn[j][2 * i + 1] + uy * (hold.y - Rn[j][2 * i + 1]);
                *(float2*)(hS + r * 256 + cidx) = hn;
                *(float2*)(g_hs + ((size_t)(row0 + r) * D + t) * HDIM + cidx) = hn;
            }
        }
        __syncthreads();
    }
}

// ---------------------------------------------------------------------------
// Kernel 3: fused MLP + mixture log-likelihood. 8192 CTAs, 32 positions each.
// ---------------------------------------------------------------------------
__global__ void __launch_bounds__(256, 2) mlp_kernel(
    const float* __restrict__ z,
    const float* __restrict__ W1, const float* __restrict__ W2, const float* __restrict__ W3,
    const float* __restrict__ b2, const float* __restrict__ b3)
{
    extern __shared__ float sm[];
    float* A   = sm;              // 32*256  (hs, later a2)
    float* O   = A   + 8192;      // 32*256  (a1)
    float* Wt  = O   + 8192;      // 32*258
    float* prm = Wt  + 32 * WTS;  // 32*66
    float* c1s = prm + 32 * 66;   // 256
    float* b2s = c1s + 256;       // 256
    float* b3s = b2s + 256;       // 64
    float* zs  = b3s + 64;        // 32

    const int tid  = threadIdx.x;
    const int lane = tid & 31, w = tid >> 5;
    const int bId  = blockIdx.x >> 1;
    const int t0   = (blockIdx.x & 1) * 32;
    const size_t hbase = ((size_t)bId * D + t0) * HDIM;

    for (int i = tid; i < 8192; i += 256) A[i] = g_hs[hbase + i];
    if (tid < 256) { c1s[tid] = g_c1[(size_t)bId * HDIM + tid]; b2s[tid] = b2[tid]; }
    if (tid < 64)  b3s[tid] = (tid < 60) ? b3[tid] : 0.f;
    if (tid < 32)  zs[tid] = z[(size_t)bId * D + t0 + tid];
    __syncthreads();

    u64 acc[4][4];
    // ---- layer 1: A @ W1[:, :256]^T, +c1 (has b1 + cbm part), tanh ----
#pragma unroll
    for (int j = 0; j < 4; ++j)
#pragma unroll
        for (int i = 0; i < 4; ++i) acc[j][i] = 0ull;
    mm2_chunk256(acc, W1, 464, A, Wt, tid);
#pragma unroll
    for (int j = 0; j < 4; ++j) {
        int r = w + 8 * j;
#pragma unroll
        for (int i = 0; i < 4; ++i) {
            int cc = 2 * lane + 64 * i;
            float2 av = unpack2(acc[j][i]);
            float2 ci = *(const float2*)(c1s + cc);
            float2 ov; ov.x = ftanh(av.x + ci.x); ov.y = ftanh(av.y + ci.y);
            *(float2*)(O + r * 256 + cc) = ov;
        }
    }
    // ---- layer 2: O @ W2^T + b2, tanh -> A ----
#pragma unroll
    for (int j = 0; j < 4; ++j)
#pragma unroll
        for (int i = 0; i < 4; ++i) acc[j][i] = 0ull;
    mm2_chunk256(acc, W2, 256, O, Wt, tid);
#pragma unroll
    for (int j = 0; j < 4; ++j) {
        int r = w + 8 * j;
#pragma unroll
        for (int i = 0; i < 4; ++i) {
            int cc = 2 * lane + 64 * i;
            float2 av = unpack2(acc[j][i]);
            float2 bi = *(const float2*)(b2s + cc);
            float2 ov; ov.x = ftanh(av.x + bi.x); ov.y = ftanh(av.y + bi.y);
            *(float2*)(A + r * 256 + cc) = ov;
        }
    }
    // ---- layer 3: A @ W3^T + b3, N=60 (padded 64) ----
    u64 acc3[4];
#pragma unroll
    for (int j = 0; j < 4; ++j) acc3[j] = 0ull;
#pragma unroll 1
    for (int kt = 0; kt < 8; ++kt) {
        const int k0 = kt * 32;
#pragma unroll
        for (int it = 0; it < 8; ++it) {
            int g = it * 8 + w;                                   // 0..63
            Wt[lane * 66 + g] = (g < 60) ? W3[g * 256 + k0 + lane] : 0.f;
        }
        __syncthreads();
#pragma unroll
        for (int kk = 0; kk < 32; ++kk) {
            float s0 = A[(w +  0) * 256 + k0 + kk];
            float s1 = A[(w +  8) * 256 + k0 + kk];
            float s2 = A[(w + 16) * 256 + k0 + kk];
            float s3 = A[(w + 24) * 256 + k0 + kk];
            u64 a0 = pack2(s0, s0), a1 = pack2(s1, s1);
            u64 a2 = pack2(s2, s2), a3 = pack2(s3, s3);
            u64 wp = *(const u64*)(Wt + kk * 66 + 2 * lane);
            ffma2(acc3[0], a0, wp);
            ffma2(acc3[1], a1, wp);
            ffma2(acc3[2], a2, wp);
            ffma2(acc3[3], a3, wp);
        }
        __syncthreads();
    }
#pragma unroll
    for (int j = 0; j < 4; ++j) {
        int r = w + 8 * j;
        int cc = 2 * lane;
        float2 av = unpack2(acc3[j]);
        float2 bi = *(const float2*)(b3s + cc);
        float2 ov; ov.x = av.x + bi.x; ov.y = av.y + bi.y;
        *(float2*)(prm + r * 66 + cc) = ov;
    }
    __syncthreads();

    // ---- mixture log-likelihood epilogue (1 thread per row; accurate exp/log) ----
    if (tid < 32) {
        const int row = tid;
        const float zt = zs[row];
        const float HALF_L2PI = 0.91893853320467274178f;   // 0.5*log(2*pi)
        float av[NK];
        float m1 = -1e30f, m2 = -1e30f;
#pragma unroll
        for (int k = 0; k < NK; ++k) {
            float lg = prm[row * 66 + k];
            float mu = prm[row * 66 + 20 + k];
            float ls = prm[row * 66 + 40 + k];
            float dd = (zt - mu) * expf(-ls);
            float a  = lg - ls - HALF_L2PI - 0.5f * dd * dd;
            av[k] = a;
            m1 = fmaxf(m1, a);
            m2 = fmaxf(m2, lg);
        }
        float s1 = 0.f, s2 = 0.f;
#pragma unroll
        for (int k = 0; k < NK; ++k) {
            s1 += expf(av[k] - m1);
            s2 += expf(prm[row * 66 + k] - m2);
        }
        g_ll[(size_t)bId * D + t0 + row] = (m1 + logf(s1)) - (m2 + logf(s2));
    }
}

// ---------------------------------------------------------------------------
// Kernel 4: masked sum (sort of 0/1 mask == prefix count). One warp per row.
// ---------------------------------------------------------------------------
__global__ void reduce_kernel(const float* __restrict__ bmat,
                              const float* __restrict__ mmat,
                              float* __restrict__ out)
{
    int gwarp = (blockIdx.x * blockDim.x + threadIdx.x) >> 5;
    int lane  = threadIdx.x & 31;
    if (gwarp >= BATCH) return;
    const float* br = bmat + (size_t)gwarp * D;
    const float* mr = mmat + (size_t)gwarp * D;
    bool q0 = (mr[lane]      > 0.5f) && (br[lane]      < 0.5f);
    bool q1 = (mr[lane + 32] > 0.5f) && (br[lane + 32] < 0.5f);
    int count = __popc(__ballot_sync(0xffffffffu, q0))
              + __popc(__ballot_sync(0xffffffffu, q1));
    float s = 0.f;
    const float* ll = g_ll + (size_t)gwarp * D;
    if (lane      < count) s += ll[lane];
    if (lane + 32 < count) s += ll[lane + 32];
#pragma unroll
    for (int off = 16; off > 0; off >>= 1)
        s += __shfl_xor_sync(0xffffffffu, s, off);
    if (lane == 0) out[gwarp] = s;
}

// ---------------------------------------------------------------------------
extern "C" void kernel_launch(void* const* d_in, const int* in_sizes, int n_in,
                              void* d_out, int out_size)
{
    (void)in_sizes; (void)n_in; (void)out_size;
    const float* z    = (const float*)d_in[0];
    const float* c    = (const float*)d_in[1];
    const float* b_   = (const float*)d_in[2];
    const float* m_   = (const float*)d_in[3];
    const float* W_ih = (const float*)d_in[4];
    const float* W_hh = (const float*)d_in[5];
    const float* b_ih = (const float*)d_in[6];
    const float* b_hh = (const float*)d_in[7];
    const float* W1   = (const float*)d_in[8];
    const float* b1   = (const float*)d_in[9];
    const float* W2   = (const float*)d_in[10];
    const float* b2   = (const float*)d_in[11];
    const float* W3   = (const float*)d_in[12];
    const float* b3   = (const float*)d_in[13];
    float* out = (float*)d_out;

    const size_t smem_cbm = (32 * KPAD + 32 * WTS) * sizeof(float);
    const size_t smem_gru = (32*256 + 32*768 + 32*WTS + 32*64 + 768 + 768) * sizeof(float);
    const size_t smem_mlp = (8192 + 8192 + 32*WTS + 32*66 + 256 + 256 + 64 + 32) * sizeof(float);

    cudaFuncSetAttribute((const void*)gemm_cbm_kernel,
                         cudaFuncAttributeMaxDynamicSharedMemorySize, (int)smem_cbm);
    cudaFuncSetAttribute((const void*)gru_kernel,
                         cudaFuncAttributeMaxDynamicSharedMemorySize, (int)smem_gru);
    cudaFuncSetAttribute((const void*)mlp_kernel,
                         cudaFuncAttributeMaxDynamicSharedMemorySize, (int)smem_mlp);

    gemm_cbm_kernel<<<dim3(128, 3), 256, smem_cbm>>>(c, b_, m_, W_ih, 209, 1, b_ih, 0, G3);
    gemm_cbm_kernel<<<dim3(128, 1), 256, smem_cbm>>>(c, b_, m_, W1, 464, 256, b1, 1, HDIM);
    gru_kernel<<<128, 256, smem_gru>>>(z, W_ih, W_hh, b_hh);
    mlp_kernel<<<BATCH * 2, 256, smem_mlp>>>(z, W1, W2, W3, b2, b3);
    reduce_kernel<<<(BATCH * 32) / 256, 256>>>(b_, m_, out);
}

// round 16
// speedup vs baseline: 1.1932x; 1.0145x over previous
#include <cuda_runtime.h>
#include <math.h>
#include <stdint.h>

#define BATCH 4096
#define D     64
#define HDIM  256
#define G3    768
#define KC    208
#define KPAD  224
#define NK    20
#define WTS   258          // Wt stride (even -> 8B-aligned pairs, 2-way STS conflict only)

typedef unsigned long long u64;

// ---------------- scratch (device globals: no allocation allowed) ----------------
__device__ float g_gi[(size_t)BATCH * G3];          // cbm @ W_ih[:,1:]^T + b_ih
__device__ float g_c1[(size_t)BATCH * HDIM];        // cbm @ W1[:,256:]^T + b1
__device__ float g_hs[(size_t)BATCH * D * HDIM];    // GRU hidden states
__device__ float g_ll[(size_t)BATCH * D];           // per-position log-likelihood

// ======================= packed f32x2 helpers =======================
__device__ __forceinline__ u64 pack2(float x, float y) {
    u64 r; asm("mov.b64 %0, {%1,%2};" : "=l"(r) : "f"(x), "f"(y)); return r;
}
__device__ __forceinline__ float2 unpack2(u64 v) {
    float2 f; asm("mov.b64 {%0,%1}, %2;" : "=f"(f.x), "=f"(f.y) : "l"(v)); return f;
}
__device__ __forceinline__ void ffma2(u64& d, u64 a, u64 b) {
    asm("fma.rn.f32x2 %0, %1, %2, %0;" : "+l"(d) : "l"(a), "l"(b));
}

// ======================= fast transcendentals =======================
__device__ __forceinline__ float fsig(float x) {
    return __fdividef(1.f, 1.f + __expf(-x));
}
__device__ __forceinline__ float ftanh(float x) {
    return 1.f - __fdividef(2.f, __expf(2.f * x) + 1.f);
}

// ---------------------------------------------------------------------------
// Packed micro-kernel (256-thr, 4 rows x 8 cols): acc[4][4] += As[32x256]*B^T
// ---------------------------------------------------------------------------
__device__ __forceinline__ void mm2_chunk256(
    u64 acc[4][4], const float* __restrict__ Bmat, int ldb,
    const float* As, float* Wt, int tid)
{
    const int lane = tid & 31;
    const int w    = tid >> 5;
#pragma unroll 1
    for (int kt = 0; kt < 8; ++kt) {
        const int k0 = kt * 32;
#pragma unroll
        for (int it = 0; it < 32; ++it) {
            int g = it * 8 + w;
            Wt[lane * WTS + g] = Bmat[g * ldb + k0 + lane];
        }
        __syncthreads();
#pragma unroll
        for (int kk = 0; kk < 32; ++kk) {
            float s0 = As[(w +  0) * 256 + k0 + kk];
            float s1 = As[(w +  8) * 256 + k0 + kk];
            float s2 = As[(w + 16) * 256 + k0 + kk];
            float s3 = As[(w + 24) * 256 + k0 + kk];
            u64 a0 = pack2(s0, s0), a1 = pack2(s1, s1);
            u64 a2 = pack2(s2, s2), a3 = pack2(s3, s3);
            const float* wbase = Wt + kk * WTS + 2 * lane;
#pragma unroll
            for (int i = 0; i < 4; ++i) {
                u64 wp = *(const u64*)(wbase + 64 * i);
                ffma2(acc[0][i], a0, wp);
                ffma2(acc[1][i], a1, wp);
                ffma2(acc[2][i], a2, wp);
                ffma2(acc[3][i], a3, wp);
            }
        }
        __syncthreads();
    }
}

// ---------------------------------------------------------------------------
// GRU prefetch variant (1 CTA/SM): kt+1 W values prefetched into registers.
// ---------------------------------------------------------------------------
__device__ __forceinline__ void mm2_chunk256_pf(
    u64 acc[4][4], const float* __restrict__ Bmat, int ldb,
    const float* As, float* Wt, int tid)
{
    const int lane = tid & 31;
    const int w    = tid >> 5;
    const float* bp = Bmat + lane;
    float pre[32];
#pragma unroll
    for (int it = 0; it < 32; ++it)
        pre[it] = bp[(it * 8 + w) * ldb];
#pragma unroll 1
    for (int kt = 0; kt < 8; ++kt) {
        __syncthreads();
#pragma unroll
        for (int it = 0; it < 32; ++it)
            Wt[lane * WTS + it * 8 + w] = pre[it];
        if (kt < 7) {
            const float* bn = bp + (kt + 1) * 32;
#pragma unroll
            for (int it = 0; it < 32; ++it)
                pre[it] = bn[(it * 8 + w) * ldb];
        }
        __syncthreads();
        const int k0 = kt * 32;
#pragma unroll
        for (int kk = 0; kk < 32; ++kk) {
            float s0 = As[(w +  0) * 256 + k0 + kk];
            float s1 = As[(w +  8) * 256 + k0 + kk];
            float s2 = As[(w + 16) * 256 + k0 + kk];
            float s3 = As[(w + 24) * 256 + k0 + kk];
            u64 a0 = pack2(s0, s0), a1 = pack2(s1, s1);
            u64 a2 = pack2(s2, s2), a3 = pack2(s3, s3);
            const float* wbase = Wt + kk * WTS + 2 * lane;
#pragma unroll
            for (int i = 0; i < 4; ++i) {
                u64 wp = *(const u64*)(wbase + 64 * i);
                ffma2(acc[0][i], a0, wp);
                ffma2(acc[1][i], a1, wp);
                ffma2(acc[2][i], a2, wp);
                ffma2(acc[3][i], a3, wp);
            }
        }
    }
    __syncthreads();
}

// ---------------------------------------------------------------------------
// MLP micro-kernel: 128 threads, 8 rows x 8 cols per thread. acc[8][4].
// B tile read once per warp covers 8 rows -> crossbar/FMA = 1.0.
// ---------------------------------------------------------------------------
__device__ __forceinline__ void mm8_chunk256(
    u64 acc[8][4], const float* __restrict__ Bmat, int ldb,
    const float* As, float* Wt, int tid)
{
    const int lane = tid & 31;
    const int w2   = tid >> 5;               // 0..3
#pragma unroll 1
    for (int kt = 0; kt < 8; ++kt) {
        const int k0 = kt * 32;
#pragma unroll
        for (int it = 0; it < 64; ++it) {
            int g = it * 4 + w2;             // 0..255
            Wt[lane * WTS + g] = Bmat[g * ldb + k0 + lane];
        }
        __syncthreads();
#pragma unroll
        for (int kk = 0; kk < 32; ++kk) {
            u64 a[8];
#pragma unroll
            for (int j = 0; j < 8; ++j) {
                float s = As[(w2 + 4 * j) * 256 + k0 + kk];
                a[j] = pack2(s, s);
            }
            const float* wbase = Wt + kk * WTS + 2 * lane;
#pragma unroll
            for (int i = 0; i < 4; ++i) {
                u64 wp = *(const u64*)(wbase + 64 * i);
#pragma unroll
                for (int j = 0; j < 8; ++j)
                    ffma2(acc[j][i], a[j], wp);
            }
        }
        __syncthreads();
    }
}

// ---------------------------------------------------------------------------
// Kernel 1: out = cbm @ Bmat[:, colOff:colOff+208]^T + bias   (K=208 pad 224)
// ---------------------------------------------------------------------------
__global__ void __launch_bounds__(256) gemm_cbm_kernel(
    const float* __restrict__ c, const float* __restrict__ bb, const float* __restrict__ mmat,
    const float* __restrict__ Bmat, int ldb, int colOff,
    const float* __restrict__ bias, int which, int ldout)
{
    extern __shared__ float sm[];
    float* As = sm;                 // 32*224
    float* Wt = As + 32 * KPAD;     // 32*258
    float* outp = which ? g_c1 : g_gi;

    const int tid  = threadIdx.x;
    const int lane = tid & 31, w = tid >> 5;
    const int row0 = blockIdx.x * 32;
    const int gb   = blockIdx.y * 256;

    for (int idx = tid; idx < 32 * KPAD; idx += 256) {
        int r = idx / KPAD, j = idx - r * KPAD;
        int br = row0 + r;
        float v = 0.f;
        if (j < 80)        v = c[br * 80 + j];
        else if (j < 144)  v = bb[br * 64 + (j - 80)];
        else if (j < KC)   v = mmat[br * 64 + (j - 144)];
        As[idx] = v;
    }
    __syncthreads();

    u64 acc[4][4];
#pragma unroll
    for (int j = 0; j < 4; ++j)
#pragma unroll
        for (int i = 0; i < 4; ++i) acc[j][i] = 0ull;

#pragma unroll 1
    for (int kt = 0; kt < 7; ++kt) {
        const int k0 = kt * 32;
        const int kcol = k0 + lane;
#pragma unroll
        for (int it = 0; it < 32; ++it) {
            int g = it * 8 + w;
            float v = 0.f;
            if (kcol < KC) v = Bmat[(gb + g) * ldb + colOff + kcol];
            Wt[lane * WTS + g] = v;
        }
        __syncthreads();
#pragma unroll
        for (int kk = 0; kk < 32; ++kk) {
            float s0 = As[(w +  0) * KPAD + k0 + kk];
            float s1 = As[(w +  8) * KPAD + k0 + kk];
            float s2 = As[(w + 16) * KPAD + k0 + kk];
            float s3 = As[(w + 24) * KPAD + k0 + kk];
            u64 a0 = pack2(s0, s0), a1 = pack2(s1, s1);
            u64 a2 = pack2(s2, s2), a3 = pack2(s3, s3);
            const float* wbase = Wt + kk * WTS + 2 * lane;
#pragma unroll
            for (int i = 0; i < 4; ++i) {
                u64 wp = *(const u64*)(wbase + 64 * i);
                ffma2(acc[0][i], a0, wp);
                ffma2(acc[1][i], a1, wp);
                ffma2(acc[2][i], a2, wp);
                ffma2(acc[3][i], a3, wp);
            }
        }
        __syncthreads();
    }
#pragma unroll
    for (int j = 0; j < 4; ++j) {
        int r = row0 + w + 8 * j;
#pragma unroll
        for (int i = 0; i < 4; ++i) {
            int cc = gb + 2 * lane + 64 * i;
            float2 av = unpack2(acc[j][i]);
            float2 bi = *(const float2*)(bias + cc);
            float2 ov; ov.x = av.x + bi.x; ov.y = av.y + bi.y;
            *(float2*)(outp + (size_t)r * ldout + cc) = ov;
        }
    }
}

// ---------------------------------------------------------------------------
// Kernel 2: persistent batch-split GRU (unchanged from R14 passing state).
// ---------------------------------------------------------------------------
__global__ void __launch_bounds__(256) gru_kernel(
    const float* __restrict__ z, const float* __restrict__ Wih,
    const float* __restrict__ Whh, const float* __restrict__ bhh_g)
{
    extern __shared__ float sm[];
    float* hS   = sm;                   // 32*256
    float* giS  = hS  + 32 * 256;       // 32*768
    float* Wt   = giS + 32 * 768;       // 32*258
    float* zr   = Wt  + 32 * WTS;       // 32*64
    float* wzS  = zr  + 32 * 64;        // 768
    float* bhhS = wzS + 768;            // 768

    const int tid  = threadIdx.x;
    const int lane = tid & 31, w = tid >> 5;
    const int row0 = blockIdx.x * 32;

    for (int i = tid; i < 32 * 256; i += 256) hS[i] = 0.f;
    for (int i = tid; i < 32 * 768; i += 256) giS[i] = g_gi[(size_t)row0 * G3 + i];
    for (int i = tid; i < 32 * 64;  i += 256) zr[i]  = z[(size_t)row0 * D + i];
    for (int i = tid; i < 768; i += 256) { wzS[i] = Wih[i * 209]; bhhS[i] = bhh_g[i]; }
    __syncthreads();

    float Rn[4][8];

    for (int t = 0; t < D; ++t) {
        float zp[4];
#pragma unroll
        for (int j = 0; j < 4; ++j)
            zp[j] = (t == 0) ? -1.f : zr[(w + 8 * j) * 64 + (t - 1)];

        u64 acc[4][4];
#pragma unroll
        for (int j = 0; j < 4; ++j)
#pragma unroll
            for (int i = 0; i < 4; ++i) acc[j][i] = 0ull;
        mm2_chunk256_pf(acc, Whh, 256, hS, Wt, tid);
#pragma unroll
        for (int j = 0; j < 4; ++j) {
            int r = w + 8 * j;
#pragma unroll
            for (int i = 0; i < 4; ++i) {
                int g = 2 * lane + 64 * i;
                float2 av = unpack2(acc[j][i]);
                float2 gi2 = *(const float2*)(giS + r * 768 + g);
                float2 wz2 = *(const float2*)(wzS + g);
                float2 bh2 = *(const float2*)(bhhS + g);
                Rn[j][2 * i]     = fsig(gi2.x + zp[j] * wz2.x + av.x + bh2.x);
                Rn[j][2 * i + 1] = fsig(gi2.y + zp[j] * wz2.y + av.y + bh2.y);
            }
        }
#pragma unroll
        for (int j = 0; j < 4; ++j)
#pragma unroll
            for (int i = 0; i < 4; ++i) acc[j][i] = 0ull;
        mm2_chunk256_pf(acc, Whh + 512 * 256, 256, hS, Wt, tid);
#pragma unroll
        for (int j = 0; j < 4; ++j) {
            int r = w + 8 * j;
#pragma unroll
            for (int i = 0; i < 4; ++i) {
                int g = 512 + 2 * lane + 64 * i;
                float2 av = unpack2(acc[j][i]);
                float2 gi2 = *(const float2*)(giS + r * 768 + g);
                float2 wz2 = *(const float2*)(wzS + g);
                float2 bh2 = *(const float2*)(bhhS + g);
                float nx = gi2.x + zp[j] * wz2.x + Rn[j][2 * i]     * (av.x + bh2.x);
                float ny = gi2.y + zp[j] * wz2.y + Rn[j][2 * i + 1] * (av.y + bh2.y);
                Rn[j][2 * i]     = ftanh(nx);
                Rn[j][2 * i + 1] = ftanh(ny);
            }
        }
#pragma unroll
        for (int j = 0; j < 4; ++j)
#pragma unroll
            for (int i = 0; i < 4; ++i) acc[j][i] = 0ull;
        mm2_chunk256_pf(acc, Whh + 256 * 256, 256, hS, Wt, tid);
#pragma unroll
        for (int j = 0; j < 4; ++j) {
            int r = w + 8 * j;
#pragma unroll
            for (int i = 0; i < 4; ++i) {
                int cidx = 2 * lane + 64 * i;
                int g = 256 + cidx;
                float2 av = unpack2(acc[j][i]);
                float2 gi2 = *(const float2*)(giS + r * 768 + g);
                float2 wz2 = *(const float2*)(wzS + g);
                float2 bh2 = *(const float2*)(bhhS + g);
                float ux = fsig(gi2.x + zp[j] * wz2.x + av.x + bh2.x);
                float uy = fsig(gi2.y + zp[j] * wz2.y + av.y + bh2.y);
                float2 hold = *(const float2*)(hS + r * 256 + cidx);
                float2 hn;
                hn.x = Rn[j][2 * i]     + ux * (hold.x - Rn[j][2 * i]);
                hn.y = Rn[j][2 * i + 1] + uy * (hold.y - Rn[j][2 * i + 1]);
                *(float2*)(hS + r * 256 + cidx) = hn;
                *(float2*)(g_hs + ((size_t)(row0 + r) * D + t) * HDIM + cidx) = hn;
            }
        }
        __syncthreads();
    }
}

// ---------------------------------------------------------------------------
// Kernel 3: fused MLP + loglik. 8192 CTAs x 128 threads (4 CTAs/SM),
// 8 rows x 8 cols per thread.
// ---------------------------------------------------------------------------
__global__ void __launch_bounds__(128, 4) mlp_kernel(
    const float* __restrict__ z,
    const float* __restrict__ W1, const float* __restrict__ W2, const float* __restrict__ W3,
    const float* __restrict__ b2, const float* __restrict__ b3)
{
    extern __shared__ float sm[];
    float* A   = sm;              // 32*256  (hs, later a2)
    float* O   = A   + 8192;      // 32*256  (a1)
    float* Wt  = O   + 8192;      // 32*258
    float* prm = Wt  + 32 * WTS;  // 32*66
    float* c1s = prm + 32 * 66;   // 256
    float* b2s = c1s + 256;       // 256
    float* b3s = b2s + 256;       // 64
    float* zs  = b3s + 64;        // 32

    const int tid  = threadIdx.x;
    const int lane = tid & 31, w2 = tid >> 5;       // w2 0..3
    const int bId  = blockIdx.x >> 1;
    const int t0   = (blockIdx.x & 1) * 32;
    const size_t hbase = ((size_t)bId * D + t0) * HDIM;

    for (int i = tid; i < 8192; i += 128) A[i] = g_hs[hbase + i];
    for (int i = tid; i < 256; i += 128) {
        c1s[i] = g_c1[(size_t)bId * HDIM + i];
        b2s[i] = b2[i];
    }
    if (tid < 64)  b3s[tid] = (tid < 60) ? b3[tid] : 0.f;
    if (tid < 32)  zs[tid] = z[(size_t)bId * D + t0 + tid];
    __syncthreads();

    u64 acc[8][4];
    // ---- layer 1: A @ W1[:, :256]^T, +c1 (has b1 + cbm part), tanh -> O ----
#pragma unroll
    for (int j = 0; j < 8; ++j)
#pragma unroll
        for (int i = 0; i < 4; ++i) acc[j][i] = 0ull;
    mm8_chunk256(acc, W1, 464, A, Wt, tid);
#pragma unroll
    for (int j = 0; j < 8; ++j) {
        int r = w2 + 4 * j;
#pragma unroll
        for (int i = 0; i < 4; ++i) {
            int cc = 2 * lane + 64 * i;
            float2 av = unpack2(acc[j][i]);
            float2 ci = *(const float2*)(c1s + cc);
            float2 ov; ov.x = ftanh(av.x + ci.x); ov.y = ftanh(av.y + ci.y);
            *(float2*)(O + r * 256 + cc) = ov;
        }
    }
    // ---- layer 2: O @ W2^T + b2, tanh -> A ----
#pragma unroll
    for (int j = 0; j < 8; ++j)
#pragma unroll
        for (int i = 0; i < 4; ++i) acc[j][i] = 0ull;
    mm8_chunk256(acc, W2, 256, O, Wt, tid);
#pragma unroll
    for (int j = 0; j < 8; ++j) {
        int r = w2 + 4 * j;
#pragma unroll
        for (int i = 0; i < 4; ++i) {
            int cc = 2 * lane + 64 * i;
            float2 av = unpack2(acc[j][i]);
            float2 bi = *(const float2*)(b2s + cc);
            float2 ov; ov.x = ftanh(av.x + bi.x); ov.y = ftanh(av.y + bi.y);
            *(float2*)(A + r * 256 + cc) = ov;
        }
    }
    // ---- layer 3: A @ W3^T + b3, N=60 (padded 64) ----
    u64 acc3[8];
#pragma unroll
    for (int j = 0; j < 8; ++j) acc3[j] = 0ull;
#pragma unroll 1
    for (int kt = 0; kt < 8; ++kt) {
        const int k0 = kt * 32;
#pragma unroll
        for (int it = 0; it < 16; ++it) {
            int g = it * 4 + w2;                                  // 0..63
            Wt[lane * 66 + g] = (g < 60) ? W3[g * 256 + k0 + lane] : 0.f;
        }
        __syncthreads();
#pragma unroll
        for (int kk = 0; kk < 32; ++kk) {
            u64 bp = *(const u64*)(Wt + kk * 66 + 2 * lane);
#pragma unroll
            for (int j = 0; j < 8; ++j) {
                float s = A[(w2 + 4 * j) * 256 + k0 + kk];
                ffma2(acc3[j], pack2(s, s), bp);
            }
        }
        __syncthreads();
    }
#pragma unroll
    for (int j = 0; j < 8; ++j) {
        int r = w2 + 4 * j;
        int cc = 2 * lane;
        float2 av = unpack2(acc3[j]);
        float2 bi = *(const float2*)(b3s + cc);
        float2 ov; ov.x = av.x + bi.x; ov.y = av.y + bi.y;
        *(float2*)(prm + r * 66 + cc) = ov;
    }
    __syncthreads();

    // ---- mixture log-likelihood epilogue (1 thread per row; accurate exp/log) ----
    if (tid < 32) {
        const int row = tid;
        const float zt = zs[row];
        const float HALF_L2PI = 0.91893853320467274178f;   // 0.5*log(2*pi)
        float av[NK];
        float m1 = -1e30f, m2 = -1e30f;
#pragma unroll
        for (int k = 0; k < NK; ++k) {
            float lg = prm[row * 66 + k];
            float mu = prm[row * 66 + 20 + k];
            float ls = prm[row * 66 + 40 + k];
            float dd = (zt - mu) * expf(-ls);
            float a  = lg - ls - HALF_L2PI - 0.5f * dd * dd;
            av[k] = a;
            m1 = fmaxf(m1, a);
            m2 = fmaxf(m2, lg);
        }
        float s1 = 0.f, s2 = 0.f;
#pragma unroll
        for (int k = 0; k < NK; ++k) {
            s1 += expf(av[k] - m1);
            s2 += expf(prm[row * 66 + k] - m2);
        }
        g_ll[(size_t)bId * D + t0 + row] = (m1 + logf(s1)) - (m2 + logf(s2));
    }
}

// ---------------------------------------------------------------------------
// Kernel 4: masked sum (sort of 0/1 mask == prefix count). One warp per row.
// ---------------------------------------------------------------------------
__global__ void reduce_kernel(const float* __restrict__ bmat,
                              const float* __restrict__ mmat,
                              float* __restrict__ out)
{
    int gwarp = (blockIdx.x * blockDim.x + threadIdx.x) >> 5;
    int lane  = threadIdx.x & 31;
    if (gwarp >= BATCH) return;
    const float* br = bmat + (size_t)gwarp * D;
    const float* mr = mmat + (size_t)gwarp * D;
    bool q0 = (mr[lane]      > 0.5f) && (br[lane]      < 0.5f);
    bool q1 = (mr[lane + 32] > 0.5f) && (br[lane + 32] < 0.5f);
    int count = __popc(__ballot_sync(0xffffffffu, q0))
              + __popc(__ballot_sync(0xffffffffu, q1));
    float s = 0.f;
    const float* ll = g_ll + (size_t)gwarp * D;
    if (lane      < count) s += ll[lane];
    if (lane + 32 < count) s += ll[lane + 32];
#pragma unroll
    for (int off = 16; off > 0; off >>= 1)
        s += __shfl_xor_sync(0xffffffffu, s, off);
    if (lane == 0) out[gwarp] = s;
}

// ---------------------------------------------------------------------------
extern "C" void kernel_launch(void* const* d_in, const int* in_sizes, int n_in,
                              void* d_out, int out_size)
{
    (void)in_sizes; (void)n_in; (void)out_size;
    const float* z    = (const float*)d_in[0];
    const float* c    = (const float*)d_in[1];
    const float* b_   = (const float*)d_in[2];
    const float* m_   = (const float*)d_in[3];
    const float* W_ih = (const float*)d_in[4];
    const float* W_hh = (const float*)d_in[5];
    const float* b_ih = (const float*)d_in[6];
    const float* b_hh = (const float*)d_in[7];
    const float* W1   = (const float*)d_in[8];
    const float* b1   = (const float*)d_in[9];
    const float* W2   = (const float*)d_in[10];
    const float* b2   = (const float*)d_in[11];
    const float* W3   = (const float*)d_in[12];
    const float* b3   = (const float*)d_in[13];
    float* out = (float*)d_out;

    const size_t smem_cbm = (32 * KPAD + 32 * WTS) * sizeof(float);
    const size_t smem_gru = (32*256 + 32*768 + 32*WTS + 32*64 + 768 + 768) * sizeof(float);
    const size_t smem_mlp = (8192 + 8192 + 32*WTS + 32*66 + 256 + 256 + 64 + 32) * sizeof(float);

    cudaFuncSetAttribute((const void*)gemm_cbm_kernel,
                         cudaFuncAttributeMaxDynamicSharedMemorySize, (int)smem_cbm);
    cudaFuncSetAttribute((const void*)gru_kernel,
                         cudaFuncAttributeMaxDynamicSharedMemorySize, (int)smem_gru);
    cudaFuncSetAttribute((const void*)mlp_kernel,
                         cudaFuncAttributeMaxDynamicSharedMemorySize, (int)smem_mlp);

    gemm_cbm_kernel<<<dim3(128, 3), 256, smem_cbm>>>(c, b_, m_, W_ih, 209, 1, b_ih, 0, G3);
    gemm_cbm_kernel<<<dim3(128, 1), 256, smem_cbm>>>(c, b_, m_, W1, 464, 256, b1, 1, HDIM);
    gru_kernel<<<128, 256, smem_gru>>>(z, W_ih, W_hh, b_hh);
    mlp_kernel<<<BATCH * 2, 128, smem_mlp>>>(z, W1, W2, W3, b2, b3);
    reduce_kernel<<<(BATCH * 32) / 256, 256>>>(b_, m_, out);
}

// round 17
// speedup vs baseline: 1.2428x; 1.0416x over previous
#include <cuda_runtime.h>
#include <math.h>
#include <stdint.h>

#define BATCH 4096
#define D     64
#define HDIM  256
#define G3    768
#define KC    208
#define KPAD  224
#define NK    20
#define WTS   258          // Wt stride (even -> 8B-aligned pairs, 2-way STS conflict only)

typedef unsigned long long u64;

// ---------------- scratch (device globals: no allocation allowed) ----------------
__device__ float g_gi[(size_t)BATCH * G3];          // cbm @ W_ih[:,1:]^T + b_ih
__device__ float g_c1[(size_t)BATCH * HDIM];        // cbm @ W1[:,256:]^T + b1
__device__ float g_hs[(size_t)BATCH * D * HDIM];    // GRU hidden states
__device__ float g_ll[(size_t)BATCH * D];           // per-position log-likelihood

// ======================= packed f32x2 helpers =======================
__device__ __forceinline__ u64 pack2(float x, float y) {
    u64 r; asm("mov.b64 %0, {%1,%2};" : "=l"(r) : "f"(x), "f"(y)); return r;
}
__device__ __forceinline__ float2 unpack2(u64 v) {
    float2 f; asm("mov.b64 {%0,%1}, %2;" : "=f"(f.x), "=f"(f.y) : "l"(v)); return f;
}
__device__ __forceinline__ void ffma2(u64& d, u64 a, u64 b) {
    asm("fma.rn.f32x2 %0, %1, %2, %0;" : "+l"(d) : "l"(a), "l"(b));
}

// ======================= fast transcendentals =======================
__device__ __forceinline__ float fsig(float x) {
    return __fdividef(1.f, 1.f + __expf(-x));
}
__device__ __forceinline__ float ftanh(float x) {
    return 1.f - __fdividef(2.f, __expf(2.f * x) + 1.f);
}

// ---------------------------------------------------------------------------
// GRU prefetch micro-kernel (1 CTA/SM): kt+1 W values prefetched to registers.
// ---------------------------------------------------------------------------
__device__ __forceinline__ void mm2_chunk256_pf(
    u64 acc[4][4], const float* __restrict__ Bmat, int ldb,
    const float* As, float* Wt, int tid)
{
    const int lane = tid & 31;
    const int w    = tid >> 5;
    const float* bp = Bmat + lane;
    float pre[32];
#pragma unroll
    for (int it = 0; it < 32; ++it)
        pre[it] = bp[(it * 8 + w) * ldb];
#pragma unroll 1
    for (int kt = 0; kt < 8; ++kt) {
        __syncthreads();
#pragma unroll
        for (int it = 0; it < 32; ++it)
            Wt[lane * WTS + it * 8 + w] = pre[it];
        if (kt < 7) {
            const float* bn = bp + (kt + 1) * 32;
#pragma unroll
            for (int it = 0; it < 32; ++it)
                pre[it] = bn[(it * 8 + w) * ldb];
        }
        __syncthreads();
        const int k0 = kt * 32;
#pragma unroll
        for (int kk = 0; kk < 32; ++kk) {
            float s0 = As[(w +  0) * 256 + k0 + kk];
            float s1 = As[(w +  8) * 256 + k0 + kk];
            float s2 = As[(w + 16) * 256 + k0 + kk];
            float s3 = As[(w + 24) * 256 + k0 + kk];
            u64 a0 = pack2(s0, s0), a1 = pack2(s1, s1);
            u64 a2 = pack2(s2, s2), a3 = pack2(s3, s3);
            const float* wbase = Wt + kk * WTS + 2 * lane;
#pragma unroll
            for (int i = 0; i < 4; ++i) {
                u64 wp = *(const u64*)(wbase + 64 * i);
                ffma2(acc[0][i], a0, wp);
                ffma2(acc[1][i], a1, wp);
                ffma2(acc[2][i], a2, wp);
                ffma2(acc[3][i], a3, wp);
            }
        }
    }
    __syncthreads();
}

// ---------------------------------------------------------------------------
// MLP micro-kernel: 128 threads, 8 rows x 8 cols per thread. acc[8][4].
// ---------------------------------------------------------------------------
__device__ __forceinline__ void mm8_chunk256(
    u64 acc[8][4], const float* __restrict__ Bmat, int ldb,
    const float* As, float* Wt, int tid)
{
    const int lane = tid & 31;
    const int w2   = tid >> 5;               // 0..3
#pragma unroll 1
    for (int kt = 0; kt < 8; ++kt) {
        const int k0 = kt * 32;
#pragma unroll
        for (int it = 0; it < 64; ++it) {
            int g = it * 4 + w2;             // 0..255
            Wt[lane * WTS + g] = Bmat[g * ldb + k0 + lane];
        }
        __syncthreads();
#pragma unroll
        for (int kk = 0; kk < 32; ++kk) {
            u64 a[8];
#pragma unroll
            for (int j = 0; j < 8; ++j) {
                float s = As[(w2 + 4 * j) * 256 + k0 + kk];
                a[j] = pack2(s, s);
            }
            const float* wbase = Wt + kk * WTS + 2 * lane;
#pragma unroll
            for (int i = 0; i < 4; ++i) {
                u64 wp = *(const u64*)(wbase + 64 * i);
#pragma unroll
                for (int j = 0; j < 8; ++j)
                    ffma2(acc[j][i], a[j], wp);
            }
        }
        __syncthreads();
    }
}

// ---------------------------------------------------------------------------
// Kernel 1: out = cbm @ Bmat[:, colOff:colOff+208]^T + bias   (K=208 pad 224)
// ---------------------------------------------------------------------------
__global__ void __launch_bounds__(256) gemm_cbm_kernel(
    const float* __restrict__ c, const float* __restrict__ bb, const float* __restrict__ mmat,
    const float* __restrict__ Bmat, int ldb, int colOff,
    const float* __restrict__ bias, int which, int ldout)
{
    extern __shared__ float sm[];
    float* As = sm;                 // 32*224
    float* Wt = As + 32 * KPAD;     // 32*258
    float* outp = which ? g_c1 : g_gi;

    const int tid  = threadIdx.x;
    const int lane = tid & 31, w = tid >> 5;
    const int row0 = blockIdx.x * 32;
    const int gb   = blockIdx.y * 256;

    for (int idx = tid; idx < 32 * KPAD; idx += 256) {
        int r = idx / KPAD, j = idx - r * KPAD;
        int br = row0 + r;
        float v = 0.f;
        if (j < 80)        v = c[br * 80 + j];
        else if (j < 144)  v = bb[br * 64 + (j - 80)];
        else if (j < KC)   v = mmat[br * 64 + (j - 144)];
        As[idx] = v;
    }
    __syncthreads();

    u64 acc[4][4];
#pragma unroll
    for (int j = 0; j < 4; ++j)
#pragma unroll
        for (int i = 0; i < 4; ++i) acc[j][i] = 0ull;

#pragma unroll 1
    for (int kt = 0; kt < 7; ++kt) {
        const int k0 = kt * 32;
        const int kcol = k0 + lane;
#pragma unroll
        for (int it = 0; it < 32; ++it) {
            int g = it * 8 + w;
            float v = 0.f;
            if (kcol < KC) v = Bmat[(gb + g) * ldb + colOff + kcol];
            Wt[lane * WTS + g] = v;
        }
        __syncthreads();
#pragma unroll
        for (int kk = 0; kk < 32; ++kk) {
            float s0 = As[(w +  0) * KPAD + k0 + kk];
            float s1 = As[(w +  8) * KPAD + k0 + kk];
            float s2 = As[(w + 16) * KPAD + k0 + kk];
            float s3 = As[(w + 24) * KPAD + k0 + kk];
            u64 a0 = pack2(s0, s0), a1 = pack2(s1, s1);
            u64 a2 = pack2(s2, s2), a3 = pack2(s3, s3);
            const float* wbase = Wt + kk * WTS + 2 * lane;
#pragma unroll
            for (int i = 0; i < 4; ++i) {
                u64 wp = *(const u64*)(wbase + 64 * i);
                ffma2(acc[0][i], a0, wp);
                ffma2(acc[1][i], a1, wp);
                ffma2(acc[2][i], a2, wp);
                ffma2(acc[3][i], a3, wp);
            }
        }
        __syncthreads();
    }
#pragma unroll
    for (int j = 0; j < 4; ++j) {
        int r = row0 + w + 8 * j;
#pragma unroll
        for (int i = 0; i < 4; ++i) {
            int cc = gb + 2 * lane + 64 * i;
            float2 av = unpack2(acc[j][i]);
            float2 bi = *(const float2*)(bias + cc);
            float2 ov; ov.x = av.x + bi.x; ov.y = av.y + bi.y;
            *(float2*)(outp + (size_t)r * ldout + cc) = ov;
        }
    }
}

// ---------------------------------------------------------------------------
// Kernel 2: persistent batch-split GRU (unchanged from R15 passing state).
// ---------------------------------------------------------------------------
__global__ void __launch_bounds__(256) gru_kernel(
    const float* __restrict__ z, const float* __restrict__ Wih,
    const float* __restrict__ Whh, const float* __restrict__ bhh_g)
{
    extern __shared__ float sm[];
    float* hS   = sm;                   // 32*256
    float* giS  = hS  + 32 * 256;       // 32*768
    float* Wt   = giS + 32 * 768;       // 32*258
    float* zr   = Wt  + 32 * WTS;       // 32*64
    float* wzS  = zr  + 32 * 64;        // 768
    float* bhhS = wzS + 768;            // 768

    const int tid  = threadIdx.x;
    const int lane = tid & 31, w = tid >> 5;
    const int row0 = blockIdx.x * 32;

    for (int i = tid; i < 32 * 256; i += 256) hS[i] = 0.f;
    for (int i = tid; i < 32 * 768; i += 256) giS[i] = g_gi[(size_t)row0 * G3 + i];
    for (int i = tid; i < 32 * 64;  i += 256) zr[i]  = z[(size_t)row0 * D + i];
    for (int i = tid; i < 768; i += 256) { wzS[i] = Wih[i * 209]; bhhS[i] = bhh_g[i]; }
    __syncthreads();

    float Rn[4][8];

    for (int t = 0; t < D; ++t) {
        float zp[4];
#pragma unroll
        for (int j = 0; j < 4; ++j)
            zp[j] = (t == 0) ? -1.f : zr[(w + 8 * j) * 64 + (t - 1)];

        u64 acc[4][4];
#pragma unroll
        for (int j = 0; j < 4; ++j)
#pragma unroll
            for (int i = 0; i < 4; ++i) acc[j][i] = 0ull;
        mm2_chunk256_pf(acc, Whh, 256, hS, Wt, tid);
#pragma unroll
        for (int j = 0; j < 4; ++j) {
            int r = w + 8 * j;
#pragma unroll
            for (int i = 0; i < 4; ++i) {
                int g = 2 * lane + 64 * i;
                float2 av = unpack2(acc[j][i]);
                float2 gi2 = *(const float2*)(giS + r * 768 + g);
                float2 wz2 = *(const float2*)(wzS + g);
                float2 bh2 = *(const float2*)(bhhS + g);
                Rn[j][2 * i]     = fsig(gi2.x + zp[j] * wz2.x + av.x + bh2.x);
                Rn[j][2 * i + 1] = fsig(gi2.y + zp[j] * wz2.y + av.y + bh2.y);
            }
        }
#pragma unroll
        for (int j = 0; j < 4; ++j)
#pragma unroll
            for (int i = 0; i < 4; ++i) acc[j][i] = 0ull;
        mm2_chunk256_pf(acc, Whh + 512 * 256, 256, hS, Wt, tid);
#pragma unroll
        for (int j = 0; j < 4; ++j) {
            int r = w + 8 * j;
#pragma unroll
            for (int i = 0; i < 4; ++i) {
                int g = 512 + 2 * lane + 64 * i;
                float2 av = unpack2(acc[j][i]);
                float2 gi2 = *(const float2*)(giS + r * 768 + g);
                float2 wz2 = *(const float2*)(wzS + g);
                float2 bh2 = *(const float2*)(bhhS + g);
                float nx = gi2.x + zp[j] * wz2.x + Rn[j][2 * i]     * (av.x + bh2.x);
                float ny = gi2.y + zp[j] * wz2.y + Rn[j][2 * i + 1] * (av.y + bh2.y);
                Rn[j][2 * i]     = ftanh(nx);
                Rn[j][2 * i + 1] = ftanh(ny);
            }
        }
#pragma unroll
        for (int j = 0; j < 4; ++j)
#pragma unroll
            for (int i = 0; i < 4; ++i) acc[j][i] = 0ull;
        mm2_chunk256_pf(acc, Whh + 256 * 256, 256, hS, Wt, tid);
#pragma unroll
        for (int j = 0; j < 4; ++j) {
            int r = w + 8 * j;
#pragma unroll
            for (int i = 0; i < 4; ++i) {
                int cidx = 2 * lane + 64 * i;
                int g = 256 + cidx;
                float2 av = unpack2(acc[j][i]);
                float2 gi2 = *(const float2*)(giS + r * 768 + g);
                float2 wz2 = *(const float2*)(wzS + g);
                float2 bh2 = *(const float2*)(bhhS + g);
                float ux = fsig(gi2.x + zp[j] * wz2.x + av.x + bh2.x);
                float uy = fsig(gi2.y + zp[j] * wz2.y + av.y + bh2.y);
                float2 hold = *(const float2*)(hS + r * 256 + cidx);
                float2 hn;
                hn.x = Rn[j][2 * i]     + ux * (hold.x - Rn[j][2 * i]);
                hn.y = Rn[j][2 * i + 1] + uy * (hold.y - Rn[j][2 * i + 1]);
                *(float2*)(hS + r * 256 + cidx) = hn;
                *(float2*)(g_hs + ((size_t)(row0 + r) * D + t) * HDIM + cidx) = hn;
            }
        }
        __syncthreads();
    }
}

// ---------------------------------------------------------------------------
// Kernel 3: fused MLP + loglik. 8192 CTAs x 128 threads, 3 CTAs/SM.
// In-place activations (no O buffer); prm overlays Wt. 68 KB smem/CTA.
// ---------------------------------------------------------------------------
__global__ void __launch_bounds__(128, 3) mlp_kernel(
    const float* __restrict__ z,
    const float* __restrict__ W1, const float* __restrict__ W2, const float* __restrict__ W3,
    const float* __restrict__ b2, const float* __restrict__ b3)
{
    extern __shared__ float sm[];
    float* A   = sm;              // 32*256  (activations, reused across layers)
    float* Wt  = A   + 8192;      // 32*258  (W stage; prm overlays after layer 3)
    float* prm = Wt;              // 32*66   (overlay: written after Wt's last read)
    float* c1s = Wt  + 32 * WTS;  // 256
    float* b2s = c1s + 256;       // 256
    float* b3s = b2s + 256;       // 64
    float* zs  = b3s + 64;        // 32

    const int tid  = threadIdx.x;
    const int lane = tid & 31, w2 = tid >> 5;       // w2 0..3
    const int bId  = blockIdx.x >> 1;
    const int t0   = (blockIdx.x & 1) * 32;
    const size_t hbase = ((size_t)bId * D + t0) * HDIM;

    for (int i = tid; i < 8192; i += 128) A[i] = g_hs[hbase + i];
    for (int i = tid; i < 256; i += 128) {
        c1s[i] = g_c1[(size_t)bId * HDIM + i];
        b2s[i] = b2[i];
    }
    if (tid < 64)  b3s[tid] = (tid < 60) ? b3[tid] : 0.f;
    if (tid < 32)  zs[tid] = z[(size_t)bId * D + t0 + tid];
    __syncthreads();

    u64 acc[8][4];
    // ---- layer 1: A @ W1[:, :256]^T, +c1 (has b1 + cbm part), tanh -> A (in place) ----
#pragma unroll
    for (int j = 0; j < 8; ++j)
#pragma unroll
        for (int i = 0; i < 4; ++i) acc[j][i] = 0ull;
    mm8_chunk256(acc, W1, 464, A, Wt, tid);
    // trailing sync in mm8 guarantees all reads of A are complete
#pragma unroll
    for (int j = 0; j < 8; ++j) {
        int r = w2 + 4 * j;
#pragma unroll
        for (int i = 0; i < 4; ++i) {
            int cc = 2 * lane + 64 * i;
            float2 av = unpack2(acc[j][i]);
            float2 ci = *(const float2*)(c1s + cc);
            float2 ov; ov.x = ftanh(av.x + ci.x); ov.y = ftanh(av.y + ci.y);
            *(float2*)(A + r * 256 + cc) = ov;
        }
    }
    // layer 2's first staging __syncthreads orders these writes before rereads
    // ---- layer 2: A @ W2^T + b2, tanh -> A (in place) ----
#pragma unroll
    for (int j = 0; j < 8; ++j)
#pragma unroll
        for (int i = 0; i < 4; ++i) acc[j][i] = 0ull;
    mm8_chunk256(acc, W2, 256, A, Wt, tid);
#pragma unroll
    for (int j = 0; j < 8; ++j) {
        int r = w2 + 4 * j;
#pragma unroll
        for (int i = 0; i < 4; ++i) {
            int cc = 2 * lane + 64 * i;
            float2 av = unpack2(acc[j][i]);
            float2 bi = *(const float2*)(b2s + cc);
            float2 ov; ov.x = ftanh(av.x + bi.x); ov.y = ftanh(av.y + bi.y);
            *(float2*)(A + r * 256 + cc) = ov;
        }
    }
    // ---- layer 3: A @ W3^T + b3, N=60 (padded 64) ----
    u64 acc3[8];
#pragma unroll
    for (int j = 0; j < 8; ++j) acc3[j] = 0ull;
#pragma unroll 1
    for (int kt = 0; kt < 8; ++kt) {
        const int k0 = kt * 32;
        __syncthreads();            // prior A-writes / prior-kt reads done
#pragma unroll
        for (int it = 0; it < 16; ++it) {
            int g = it * 4 + w2;                                  // 0..63
            Wt[lane * 66 + g] = (g < 60) ? W3[g * 256 + k0 + lane] : 0.f;
        }
        __syncthreads();
#pragma unroll
        for (int kk = 0; kk < 32; ++kk) {
            u64 bp = *(const u64*)(Wt + kk * 66 + 2 * lane);
#pragma unroll
            for (int j = 0; j < 8; ++j) {
                float s = A[(w2 + 4 * j) * 256 + k0 + kk];
                ffma2(acc3[j], pack2(s, s), bp);
            }
        }
    }
    __syncthreads();                // Wt's last read done -> prm overlay safe
#pragma unroll
    for (int j = 0; j < 8; ++j) {
        int r = w2 + 4 * j;
        int cc = 2 * lane;
        float2 av = unpack2(acc3[j]);
        float2 bi = *(const float2*)(b3s + cc);
        float2 ov; ov.x = av.x + bi.x; ov.y = av.y + bi.y;
        *(float2*)(prm + r * 66 + cc) = ov;
    }
    __syncthreads();

    // ---- mixture log-likelihood epilogue (1 thread per row; accurate exp/log) ----
    if (tid < 32) {
        const int row = tid;
        const float zt = zs[row];
        const float HALF_L2PI = 0.91893853320467274178f;   // 0.5*log(2*pi)
        float av[NK];
        float m1 = -1e30f, m2 = -1e30f;
#pragma unroll
        for (int k = 0; k < NK; ++k) {
            float lg = prm[row * 66 + k];
            float mu = prm[row * 66 + 20 + k];
            float ls = prm[row * 66 + 40 + k];
            float dd = (zt - mu) * expf(-ls);
            float a  = lg - ls - HALF_L2PI - 0.5f * dd * dd;
            av[k] = a;
            m1 = fmaxf(m1, a);
            m2 = fmaxf(m2, lg);
        }
        float s1 = 0.f, s2 = 0.f;
#pragma unroll
        for (int k = 0; k < NK; ++k) {
            s1 += expf(av[k] - m1);
            s2 += expf(prm[row * 66 + k] - m2);
        }
        g_ll[(size_t)bId * D + t0 + row] = (m1 + logf(s1)) - (m2 + logf(s2));
    }
}

// ---------------------------------------------------------------------------
// Kernel 4: masked sum (sort of 0/1 mask == prefix count). One warp per row.
// ---------------------------------------------------------------------------
__global__ void reduce_kernel(const float* __restrict__ bmat,
                              const float* __restrict__ mmat,
                              float* __restrict__ out)
{
    int gwarp = (blockIdx.x * blockDim.x + threadIdx.x) >> 5;
    int lane  = threadIdx.x & 31;
    if (gwarp >= BATCH) return;
    const float* br = bmat + (size_t)gwarp * D;
    const float* mr = mmat + (size_t)gwarp * D;
    bool q0 = (mr[lane]      > 0.5f) && (br[lane]      < 0.5f);
    bool q1 = (mr[lane + 32] > 0.5f) && (br[lane + 32] < 0.5f);
    int count = __popc(__ballot_sync(0xffffffffu, q0))
              + __popc(__ballot_sync(0xffffffffu, q1));
    float s = 0.f;
    const float* ll = g_ll + (size_t)gwarp * D;
    if (lane      < count) s += ll[lane];
    if (lane + 32 < count) s += ll[lane + 32];
#pragma unroll
    for (int off = 16; off > 0; off >>= 1)
        s += __shfl_xor_sync(0xffffffffu, s, off);
    if (lane == 0) out[gwarp] = s;
}

// ---------------------------------------------------------------------------
extern "C" void kernel_launch(void* const* d_in, const int* in_sizes, int n_in,
                              void* d_out, int out_size)
{
    (void)in_sizes; (void)n_in; (void)out_size;
    const float* z    = (const float*)d_in[0];
    const float* c    = (const float*)d_in[1];
    const float* b_   = (const float*)d_in[2];
    const float* m_   = (const float*)d_in[3];
    const float* W_ih = (const float*)d_in[4];
    const float* W_hh = (const float*)d_in[5];
    const float* b_ih = (const float*)d_in[6];
    const float* b_hh = (const float*)d_in[7];
    const float* W1   = (const float*)d_in[8];
    const float* b1   = (const float*)d_in[9];
    const float* W2   = (const float*)d_in[10];
    const float* b2   = (const float*)d_in[11];
    const float* W3   = (const float*)d_in[12];
    const float* b3   = (const float*)d_in[13];
    float* out = (float*)d_out;

    const size_t smem_cbm = (32 * KPAD + 32 * WTS) * sizeof(float);
    const size_t smem_gru = (32*256 + 32*768 + 32*WTS + 32*64 + 768 + 768) * sizeof(float);
    const size_t smem_mlp = (8192 + 32 * WTS + 256 + 256 + 64 + 32) * sizeof(float);

    cudaFuncSetAttribute((const void*)gemm_cbm_kernel,
                         cudaFuncAttributeMaxDynamicSharedMemorySize, (int)smem_cbm);
    cudaFuncSetAttribute((const void*)gru_kernel,
                         cudaFuncAttributeMaxDynamicSharedMemorySize, (int)smem_gru);
    cudaFuncSetAttribute((const void*)mlp_kernel,
                         cudaFuncAttributeMaxDynamicSharedMemorySize, (int)smem_mlp);

    gemm_cbm_kernel<<<dim3(128, 3), 256, smem_cbm>>>(c, b_, m_, W_ih, 209, 1, b_ih, 0, G3);
    gemm_cbm_kernel<<<dim3(128, 1), 256, smem_cbm>>>(c, b_, m_, W1, 464, 256, b1, 1, HDIM);
    gru_kernel<<<128, 256, smem_gru>>>(z, W_ih, W_hh, b_hh);
    mlp_kernel<<<BATCH * 2, 128, smem_mlp>>>(z, W1, W2, W3, b2, b3);
    reduce_kernel<<<(BATCH * 32) / 256, 256>>>(b_, m_, out);
}